// round 11
// baseline (speedup 1.0000x reference)
#include <cuda_runtime.h>
#include <math.h>

#define Nn 16384
#define Bg 16
#define Hd 64
#define H2 128
#define Kn 16
#define DPAD 1568
#define MAXT 1600
#define BN_EPS 1e-5f

// packed f32x2 helpers (bit-exact pairs of IEEE fp32 FMAs)
#define FMA2(acc, a, b) asm("fma.rn.f32x2 %0, %1, %2, %0;" : "+l"(acc) : "l"(a), "l"(b))
#define PACKF2(dst, x)  asm("mov.b64 %0, {%1, %1};" : "=l"(dst) : "r"(__float_as_uint(x)))
#define UNPACKF2(lo, hi, src) asm("mov.b64 {%0, %1}, %2;" : "=r"(lo), "=r"(hi) : "l"(src))

// ---------------- scratch ----------------
__device__ float d_h[Nn*Hd];
__device__ float d_e[Nn*Hd];
__device__ float d_hT[Hd*Nn];
__device__ float d_u[Nn*H2];
__device__ float d_v[Nn*H2];
__device__ float d_sq[Nn];
__device__ float d_g[Bg*Hd];
__device__ int   d_idx[Nn*Kn];
__device__ int   d_partner[Nn];
__device__ int   d_validA[Nn];
__device__ int   d_validB[Nn];
__device__ int   d_gstart[Bg+1];
__device__ int   d_glist[Nn];
__device__ int   d_gcount[Bg];

// ---------------- graph bounds ----------------
__global__ void k_bounds(const int* __restrict__ batch){
    int b = threadIdx.x;
    if (b > Bg) return;
    if (b == Bg){ d_gstart[Bg] = Nn; return; }
    int lo = 0, hi = Nn;
    while (lo < hi){ int mid = (lo + hi) >> 1; if (batch[mid] < b) lo = mid + 1; else hi = mid; }
    d_gstart[b] = lo;
}

// ---------------- input net ----------------
__global__ void k_input(const float* __restrict__ x, const float* __restrict__ dn,
                        const float* __restrict__ w, const float* __restrict__ b){
    int tid = blockIdx.x*256 + threadIdx.x;
    int i = tid >> 6, c = tid & 63;
    float acc = __ldg(&b[c]);
    #pragma unroll
    for (int d = 0; d < 4; d++) acc += x[i*4+d] * __ldg(&dn[d]) * __ldg(&w[c*4+d]);
    d_h[i*Hd+c] = fmaxf(acc, 0.f);
}

__global__ void k_init(){
    int i = blockIdx.x*blockDim.x + threadIdx.x;
    if (i < Nn){ d_validA[i] = 1; d_glist[i] = i; d_sq[i] = 0.f; }
    if (i < Bg) d_gcount[i] = d_gstart[i+1] - d_gstart[i];
}

// ---------------- transpose + fused squared norms (2-addend atomicAdd: deterministic) ----------------
__global__ void k_transpose(int layer){
    const float* h = layer ? d_e : d_h;
    __shared__ float tile[32][33];
    int n0 = blockIdx.x*32, d0 = blockIdx.y*32;
    int tx = threadIdx.x, ty = threadIdx.y;       // (32,8)
    #pragma unroll
    for (int r = ty; r < 32; r += 8) tile[r][tx] = h[(n0+r)*Hd + d0 + tx];
    __syncthreads();
    #pragma unroll
    for (int r = ty; r < 32; r += 8) d_hT[(d0+r)*Nn + n0 + tx] = tile[tx][r];
    if (ty == 0){
        float ssum = 0.f;
        #pragma unroll 8
        for (int k = 0; k < 32; k++){ float v = tile[tx][k]; ssum = fmaf(v, v, ssum); }
        atomicAdd(&d_sq[n0+tx], ssum);
    }
}

// ---------------- kNN: 16 queries/block, f32x2 distance, warp-per-query top-16 ----------------
extern __shared__ float knn_smem[];
__global__ void __launch_bounds__(512) k_knn(int layer){
    const float* h = layer ? d_e : d_h;
    float* dbuf = knn_smem;                 // [16][DPAD]
    float* hq   = knn_smem + 16*DPAD;       // [64][16]
    __shared__ int   qidx[16];
    __shared__ float sqq[16];
    __shared__ int   sh_g, sh_qs0;

    int tid = threadIdx.x;
    if (tid == 0){
        int bt = blockIdx.x, acc = 0, gg = -1, qq0 = 0;
        for (int g2 = 0; g2 < Bg; g2++){
            int cg = d_gcount[g2]; if (cg > DPAD) cg = DPAD;
            int tiles = (cg + 15) >> 4;
            if (bt < acc + tiles){ gg = g2; qq0 = (bt - acc)*16; break; }
            acc += tiles;
        }
        sh_g = gg; sh_qs0 = qq0;
    }
    __syncthreads();
    if (sh_g < 0) return;
    int g = sh_g, qs0 = sh_qs0;
    int p0  = d_gstart[g];
    int cnt = d_gcount[g]; if (cnt > DPAD) cnt = DPAD;
    int nq  = cnt - qs0; if (nq > 16) nq = 16;

    if (tid < 256){
        int q = tid >> 4, d4 = (tid & 15) << 2;
        int qq = (q < nq) ? q : (nq - 1);
        int qi = d_glist[p0 + qs0 + qq];
        float4 v = *(const float4*)&h[qi*Hd + d4];
        hq[(d4+0)*16+q] = v.x; hq[(d4+1)*16+q] = v.y;
        hq[(d4+2)*16+q] = v.z; hq[(d4+3)*16+q] = v.w;
        if (d4 == 0){ qidx[q] = qi; sqq[q] = d_sq[qi]; }
    }
    __syncthreads();

    for (int c0 = 0; c0 < cnt; c0 += 1024){
        int ca = c0 + tid, cb = ca + 512;
        int ja = (ca < cnt) ? d_glist[p0+ca] : d_glist[p0];
        int jb = (cb < cnt) ? d_glist[p0+cb] : d_glist[p0];
        unsigned long long A2[8], B2[8];
        #pragma unroll
        for (int q = 0; q < 8; q++){ A2[q] = 0ULL; B2[q] = 0ULL; }
        const float* pa = d_hT + ja;
        const float* pb = d_hT + jb;
        const ulonglong2* hrp = (const ulonglong2*)hq;
        #pragma unroll 2
        for (int d = 0; d < Hd; d++){
            float va = *pa; pa += Nn;
            float vb = *pb; pb += Nn;
            unsigned long long va2, vb2;
            PACKF2(va2, va); PACKF2(vb2, vb);
            ulonglong2 qA = hrp[0], qB = hrp[1], qC = hrp[2], qD = hrp[3];
            hrp += 4;
            FMA2(A2[0], qA.x, va2); FMA2(A2[1], qA.y, va2);
            FMA2(A2[2], qB.x, va2); FMA2(A2[3], qB.y, va2);
            FMA2(A2[4], qC.x, va2); FMA2(A2[5], qC.y, va2);
            FMA2(A2[6], qD.x, va2); FMA2(A2[7], qD.y, va2);
            FMA2(B2[0], qA.x, vb2); FMA2(B2[1], qA.y, vb2);
            FMA2(B2[2], qB.x, vb2); FMA2(B2[3], qB.y, vb2);
            FMA2(B2[4], qC.x, vb2); FMA2(B2[5], qC.y, vb2);
            FMA2(B2[6], qD.x, vb2); FMA2(B2[7], qD.y, vb2);
        }
        if (ca < cnt){
            float sqa = d_sq[ja];
            #pragma unroll
            for (int q = 0; q < 8; q++){
                unsigned int lo, hi; UNPACKF2(lo, hi, A2[q]);
                dbuf[(2*q  )*DPAD+ca] = sqq[2*q  ] + sqa - 2.f*__uint_as_float(lo);
                dbuf[(2*q+1)*DPAD+ca] = sqq[2*q+1] + sqa - 2.f*__uint_as_float(hi);
            }
        }
        if (cb < cnt){
            float sqb = d_sq[jb];
            #pragma unroll
            for (int q = 0; q < 8; q++){
                unsigned int lo, hi; UNPACKF2(lo, hi, B2[q]);
                dbuf[(2*q  )*DPAD+cb] = sqq[2*q  ] + sqb - 2.f*__uint_as_float(lo);
                dbuf[(2*q+1)*DPAD+cb] = sqq[2*q+1] + sqb - 2.f*__uint_as_float(hi);
            }
        }
    }
    __syncthreads();

    int warp = tid >> 5, lane = tid & 31;
    if (warp < nq){
        float* row = &dbuf[warp*DPAD];
        int qi = qidx[warp];
        for (int r = 0; r < Kn; r++){
            float bd = INFINITY; int bp = 0x7fffffff;
            for (int c = lane; c < cnt; c += 32){
                float dd = row[c];
                if (dd < bd){ bd = dd; bp = c; }
            }
            #pragma unroll
            for (int off = 16; off > 0; off >>= 1){
                float od = __shfl_down_sync(0xffffffffu, bd, off);
                int   op = __shfl_down_sync(0xffffffffu, bp, off);
                if (od < bd || (od == bd && op < bp)){ bd = od; bp = op; }
            }
            int win = __shfl_sync(0xffffffffu, bp, 0);
            if (lane == 0) d_idx[qi*Kn + r] = d_glist[p0 + win];
            row[win] = INFINITY;
            __syncwarp();
        }
    }
}

// ---------------- edgeconv stage 1: f32x2, 4 nodes per weight read ----------------
#define UVN 16
__global__ void __launch_bounds__(128) k_uv(int layer, const float* __restrict__ l0w,
                     const float* __restrict__ l0b,
                     const float* __restrict__ g0, const float* __restrict__ b0){
    const int t = threadIdx.x;
    const int* valid = layer ? d_validB : d_validA;
    const float* h   = layer ? d_e      : d_h;
    __shared__ float Wsh[H2*129];
    __shared__ __align__(16) float hsh4[Hd*4];     // [c][node]
    for (int p = t; p < H2*H2; p += H2){
        int o = p >> 7, c = p & 127;
        Wsh[o*129 + c] = __ldg(&l0w[p]);
    }
    float s  = __ldg(&g0[t]) / sqrtf(1.0f + BN_EPS);
    float bb = __ldg(&l0b[t])*s + __ldg(&b0[t]);
    __syncthreads();

    int base = blockIdx.x * UVN;
    for (int r4 = 0; r4 < UVN; r4 += 4){
        #pragma unroll
        for (int p = t; p < 4*Hd; p += 128){
            int n = p >> 6, c = p & 63;
            int i = base + r4 + n;
            hsh4[c*4+n] = valid[i] ? h[i*Hd+c] : 0.f;
        }
        __syncthreads();
        const float* wr = &Wsh[t*129];
        unsigned long long su01 = 0ULL, su23 = 0ULL, sv01 = 0ULL, sv23 = 0ULL;
        #pragma unroll 4
        for (int c = 0; c < Hd; c++){
            float a  = wr[c];
            float bw = wr[Hd+c];
            float amb = a - bw;
            unsigned long long amb2, bw2;
            PACKF2(amb2, amb); PACKF2(bw2, bw);
            ulonglong2 hp = *(const ulonglong2*)&hsh4[c*4];
            FMA2(su01, hp.x, amb2); FMA2(su23, hp.y, amb2);
            FMA2(sv01, hp.x, bw2);  FMA2(sv23, hp.y, bw2);
        }
        unsigned int u0,u1,u2,u3, v0,v1,v2,v3;
        UNPACKF2(u0,u1,su01); UNPACKF2(u2,u3,su23);
        UNPACKF2(v0,v1,sv01); UNPACKF2(v2,v3,sv23);
        int i0 = base + r4;
        if (valid[i0  ]){ d_u[(i0  )*H2+t] = __uint_as_float(u0)*s + bb; d_v[(i0  )*H2+t] = __uint_as_float(v0)*s; }
        if (valid[i0+1]){ d_u[(i0+1)*H2+t] = __uint_as_float(u1)*s + bb; d_v[(i0+1)*H2+t] = __uint_as_float(v1)*s; }
        if (valid[i0+2]){ d_u[(i0+2)*H2+t] = __uint_as_float(u2)*s + bb; d_v[(i0+2)*H2+t] = __uint_as_float(v2)*s; }
        if (valid[i0+3]){ d_u[(i0+3)*H2+t] = __uint_as_float(u3)*s + bb; d_v[(i0+3)*H2+t] = __uint_as_float(v3)*s; }
        __syncthreads();
    }
}

// ---------------- edgeconv stage 2: f32x2 mainloop, 64-thread group per node ----------------
#define EN 16
__global__ void __launch_bounds__(256) k_edge(int layer, const float* __restrict__ l1w,
                       const float* __restrict__ l1b,
                       const float* __restrict__ g1, const float* __restrict__ b1){
    const int tid = threadIdx.x;
    const int grp = tid >> 6, t = tid & 63, lane = tid & 31;
    const int* valid = layer ? d_validB : d_validA;
    float*     out   = layer ? d_h      : d_e;

    __shared__ float W1t[H2*65];
    __shared__ __align__(16) float rsh[4][H2*16];

    for (int p = tid; p < Hd*H2; p += 256){
        int o = p >> 7, r = p & 127;
        W1t[r*65+o] = __ldg(&l1w[p]);
    }
    float s  = __ldg(&g1[t]) / sqrtf(1.0f + BN_EPS);
    float bb = __ldg(&l1b[t])*s + __ldg(&b1[t]);
    __syncthreads();

    int base = blockIdx.x * EN;
    for (int round = 0; round < 4; round++){
        int i = base + round*4 + grp;
        if (!valid[i]) continue;

        float u0 = d_u[i*H2+t], u1 = d_u[i*H2+64+t];
        int myj = (lane < Kn) ? d_idx[i*Kn+lane] : 0;
        float r0[16], r1[16];
        #pragma unroll
        for (int e = 0; e < 16; e++){
            int j = __shfl_sync(0xffffffffu, myj, e);
            r0[e] = fmaxf(u0 + __ldg(&d_v[j*H2+t]),    0.f);
            r1[e] = fmaxf(u1 + __ldg(&d_v[j*H2+64+t]), 0.f);
        }
        float* R = rsh[grp];
        #pragma unroll
        for (int q = 0; q < 4; q++){
            *(float4*)&R[t*16+q*4]      = make_float4(r0[q*4],r0[q*4+1],r0[q*4+2],r0[q*4+3]);
            *(float4*)&R[(t+64)*16+q*4] = make_float4(r1[q*4],r1[q*4+1],r1[q*4+2],r1[q*4+3]);
        }
        asm volatile("bar.sync %0, 64;" :: "r"(grp+1) : "memory");

        unsigned long long acc2[8];
        #pragma unroll
        for (int q = 0; q < 8; q++) acc2[q] = 0ULL;
        const ulonglong2* Rr = (const ulonglong2*)R;
        #pragma unroll 2
        for (int r = 0; r < H2; r++){
            ulonglong2 pA = Rr[0], pB = Rr[1], pC = Rr[2], pD = Rr[3];
            Rr += 4;
            float w = W1t[r*65+t];
            unsigned long long w2; PACKF2(w2, w);
            FMA2(acc2[0], pA.x, w2); FMA2(acc2[1], pA.y, w2);
            FMA2(acc2[2], pB.x, w2); FMA2(acc2[3], pB.y, w2);
            FMA2(acc2[4], pC.x, w2); FMA2(acc2[5], pC.y, w2);
            FMA2(acc2[6], pD.x, w2); FMA2(acc2[7], pD.y, w2);
        }
        float o = 0.f;
        #pragma unroll
        for (int q = 0; q < 8; q++){
            unsigned int lo, hi; UNPACKF2(lo, hi, acc2[q]);
            o += fmaxf(__uint_as_float(lo)*s + bb, 0.f);
            o += fmaxf(__uint_as_float(hi)*s + bb, 0.f);
        }
        out[i*Hd+t] = o;
        asm volatile("bar.sync %0, 64;" :: "r"(grp+1) : "memory");
    }
}

// ---------------- cluster pool: mutual max-distance matching ----------------
__global__ void k_partner(int layer){
    const float* h     = layer ? d_h : d_e;
    const int*   valid = layer ? d_validB : d_validA;
    int lane = threadIdx.x & 31, wid = threadIdx.x >> 5;
    int i = blockIdx.x*4 + wid;
    if (!valid[i]){ if (lane == 0) d_partner[i] = i; return; }

    int n = lane & 15, hf = lane >> 4;
    int j = d_idx[i*Kn+n];
    const float4* pj = (const float4*)&h[j*Hd + hf*32];
    const float4* pi = (const float4*)&h[i*Hd + hf*32];
    float ssum = 0.f;
    #pragma unroll
    for (int q = 0; q < 8; q++){
        float4 a = __ldg(&pj[q]);
        float4 b = pi[q];
        float dx = a.x-b.x, dy = a.y-b.y, dz = a.z-b.z, dw = a.w-b.w;
        ssum += dx*dx + dy*dy + dz*dz + dw*dw;
    }
    ssum += __shfl_xor_sync(0xffffffffu, ssum, 16);
    float w = (j == i) ? -INFINITY : sqrtf(ssum + 1e-12f);
    int bk = n;
    #pragma unroll
    for (int off = 8; off > 0; off >>= 1){
        float ow = __shfl_down_sync(0xffffffffu, w,  off);
        int   ok = __shfl_down_sync(0xffffffffu, bk, off);
        int   oj = __shfl_down_sync(0xffffffffu, j,  off);
        if (ow > w || (ow == w && ok < bk)){ w = ow; bk = ok; j = oj; }
    }
    if (lane == 0) d_partner[i] = valid[j] ? j : i;
}

// ---------------- fused pool + compaction + sq-zero (per graph) ----------------
__global__ void k_poolcompact(int layer){
    int g = blockIdx.x, t = threadIdx.x;           // 256 threads
    float* h   = layer ? d_h : d_e;
    const int* vin  = layer ? d_validB : d_validA;
    int*       vout = layer ? d_validA : d_validB;
    int s = d_gstart[g], e2 = d_gstart[g+1];

    // pool phase: 4 nodes per pass, 64 threads each
    for (int nb = s; nb < e2; nb += 4){
        int i = nb + (t >> 6);
        int c = t & 63;
        if (i < e2){
            if (!vin[i]){
                if (c == 0){ vout[i] = 0; d_sq[i] = 0.f; }
            } else {
                int p = d_partner[i];
                int keep = 1;
                if (p != i && d_partner[p] == i){
                    if (p < i) keep = 0;
                    else h[i*Hd+c] = fmaxf(h[i*Hd+c], h[p*Hd+c]);
                }
                if (c == 0){ vout[i] = keep; d_sq[i] = 0.f; }
            }
        }
    }
    __syncthreads();

    // compaction phase (order-preserving)
    int lane = t & 31, warp = t >> 5;
    __shared__ int wsum[8], woff[8], base;
    if (t == 0) base = 0;
    __syncthreads();
    for (int st = s; st < e2; st += 256){
        int node = st + t;
        int f = (node < e2) ? vout[node] : 0;
        unsigned m = __ballot_sync(0xffffffffu, f);
        int wpre = __popc(m & ((1u << lane) - 1u));
        if (lane == 0) wsum[warp] = __popc(m);
        __syncthreads();
        if (t == 0){
            int r = base;
            for (int w2 = 0; w2 < 8; w2++){ woff[w2] = r; r += wsum[w2]; }
            base = r;
        }
        __syncthreads();
        if (f) d_glist[s + woff[warp] + wpre] = node;
        __syncthreads();
    }
    if (t == 0) d_gcount[g] = base;
}

// ---------------- global max-pool ----------------
__global__ void k_globalpool(){
    int b = blockIdx.x, t = threadIdx.x;
    int c = t & 63, rg = t >> 6;
    int s = d_gstart[b], e2 = d_gstart[b+1];
    float m = -1e30f;
    for (int i = s + rg; i < e2; i += 8)
        if (d_validA[i]) m = fmaxf(m, d_h[i*Hd+c]);
    __shared__ float red[512];
    red[t] = m; __syncthreads();
    if (t < 256) red[t] = fmaxf(red[t], red[t+256]);
    __syncthreads();
    if (t < 128) red[t] = fmaxf(red[t], red[t+128]);
    __syncthreads();
    if (t < 64) d_g[b*Hd + c] = fmaxf(red[t], red[t+64]);
}

// ---------------- output MLP ----------------
__global__ void k_mlp(const float* __restrict__ o0w, const float* __restrict__ o0b,
                      const float* __restrict__ o1w, const float* __restrict__ o1b,
                      const float* __restrict__ o2w, const float* __restrict__ o2b,
                      float* __restrict__ out){
    int t = threadIdx.x;
    int b = t >> 6, c = t & 63;
    __shared__ float g1s[Bg*Hd], g2s[Bg*Hd];
    float acc = __ldg(&o0b[c]);
    for (int d = 0; d < Hd; d++) acc += d_g[b*Hd+d] * __ldg(&o0w[c*Hd+d]);
    g1s[t] = fmaxf(acc, 0.f);
    __syncthreads();
    acc = __ldg(&o1b[c]);
    for (int d = 0; d < Hd; d++) acc += g1s[b*Hd+d] * __ldg(&o1w[c*Hd+d]);
    g2s[t] = fmaxf(acc, 0.f);
    __syncthreads();
    if (t < Bg){
        float a = __ldg(&o2b[0]);
        for (int d = 0; d < Hd; d++) a += g2s[t*Hd+d] * __ldg(&o2w[d]);
        out[t] = a;
    }
}

// ---------------- launch ----------------
extern "C" void kernel_launch(void* const* d_in, const int* in_sizes, int n_in,
                              void* d_out, int out_size){
    const float* x     = (const float*)d_in[0];
    const int*   batch = (const int*)  d_in[1];
    const float* dn    = (const float*)d_in[2];
    const float* inw   = (const float*)d_in[3];
    const float* inb   = (const float*)d_in[4];
    const float* A[2][8];
    for (int l = 0; l < 2; l++)
        for (int q = 0; q < 8; q++)
            A[l][q] = (const float*)d_in[5 + l*8 + q];
    const float* o0w = (const float*)d_in[21];
    const float* o0b = (const float*)d_in[22];
    const float* o1w = (const float*)d_in[23];
    const float* o1b = (const float*)d_in[24];
    const float* o2w = (const float*)d_in[25];
    const float* o2b = (const float*)d_in[26];
    float* out = (float*)d_out;

    const int knn_smem_bytes = (16*DPAD + Hd*16) * (int)sizeof(float);
    cudaFuncSetAttribute(k_knn, cudaFuncAttributeMaxDynamicSharedMemorySize, knn_smem_bytes);

    k_bounds<<<1, 32>>>(batch);
    k_input<<<Nn/4, 256>>>(x, dn, inw, inb);
    k_init<<<(Nn + 255)/256, 256>>>();

    dim3 tgrid(Nn/32, Hd/32), tthr(32, 8);
    for (int l = 0; l < 2; l++){
        k_transpose<<<tgrid, tthr>>>(l);
        k_knn<<<MAXT, 512, knn_smem_bytes>>>(l);
        k_uv<<<(Nn + UVN - 1)/UVN, H2>>>(l, A[l][0], A[l][1], A[l][2], A[l][3]);
        k_edge<<<(Nn + EN - 1)/EN, 256>>>(l, A[l][4], A[l][5], A[l][6], A[l][7]);
        k_partner<<<Nn/4, 128>>>(l);
        k_poolcompact<<<Bg, 256>>>(l);
    }

    k_globalpool<<<Bg, 512>>>();
    k_mlp<<<1, Bg*Hd>>>(o0w, o0b, o1w, o1b, o2w, o2b, out);
}

// round 12
// speedup vs baseline: 1.0822x; 1.0822x over previous
#include <cuda_runtime.h>
#include <math.h>

#define Nn 16384
#define Bg 16
#define Hd 64
#define H2 128
#define Kn 16
#define DPAD 1568
#define MAXT 1600
#define BN_EPS 1e-5f

// packed f32x2 helpers (bit-exact pairs of IEEE fp32 FMAs)
#define FMA2(acc, a, b) asm("fma.rn.f32x2 %0, %1, %2, %0;" : "+l"(acc) : "l"(a), "l"(b))
#define PACKF2(dst, x)  asm("mov.b64 %0, {%1, %1};" : "=l"(dst) : "r"(__float_as_uint(x)))
#define UNPACKF2(lo, hi, src) asm("mov.b64 {%0, %1}, %2;" : "=r"(lo), "=r"(hi) : "l"(src))

#define KNN_FMA16(A, V, Q0, Q1, Q2, Q3) \
    A[0]=fmaf(V,Q0.x,A[0]); A[1]=fmaf(V,Q0.y,A[1]); A[2]=fmaf(V,Q0.z,A[2]); A[3]=fmaf(V,Q0.w,A[3]); \
    A[4]=fmaf(V,Q1.x,A[4]); A[5]=fmaf(V,Q1.y,A[5]); A[6]=fmaf(V,Q1.z,A[6]); A[7]=fmaf(V,Q1.w,A[7]); \
    A[8]=fmaf(V,Q2.x,A[8]); A[9]=fmaf(V,Q2.y,A[9]); A[10]=fmaf(V,Q2.z,A[10]); A[11]=fmaf(V,Q2.w,A[11]); \
    A[12]=fmaf(V,Q3.x,A[12]); A[13]=fmaf(V,Q3.y,A[13]); A[14]=fmaf(V,Q3.z,A[14]); A[15]=fmaf(V,Q3.w,A[15]);

// ---------------- scratch ----------------
__device__ float d_h[Nn*Hd];
__device__ float d_e[Nn*Hd];
__device__ float d_hT[Hd*Nn];
__device__ float d_u[Nn*H2];
__device__ float d_v[Nn*H2];
__device__ float d_sq[Nn];
__device__ float d_g[Bg*Hd];
__device__ int   d_idx[Nn*Kn];
__device__ int   d_partner[Nn];
__device__ int   d_validA[Nn];
__device__ int   d_validB[Nn];
__device__ int   d_gstart[Bg+1];
__device__ int   d_glist[Nn];
__device__ int   d_gcount[Bg];

// ---------------- graph bounds ----------------
__global__ void k_bounds(const int* __restrict__ batch){
    int b = threadIdx.x;
    if (b > Bg) return;
    if (b == Bg){ d_gstart[Bg] = Nn; return; }
    int lo = 0, hi = Nn;
    while (lo < hi){ int mid = (lo + hi) >> 1; if (batch[mid] < b) lo = mid + 1; else hi = mid; }
    d_gstart[b] = lo;
}

// ---------------- input net + init (fused) ----------------
__global__ void k_input(const float* __restrict__ x, const float* __restrict__ dn,
                        const float* __restrict__ w, const float* __restrict__ b){
    int tid = blockIdx.x*256 + threadIdx.x;
    int i = tid >> 6, c = tid & 63;
    float acc = __ldg(&b[c]);
    #pragma unroll
    for (int d = 0; d < 4; d++) acc += x[i*4+d] * __ldg(&dn[d]) * __ldg(&w[c*4+d]);
    d_h[i*Hd+c] = fmaxf(acc, 0.f);
    if (c == 0){ d_validA[i] = 1; d_glist[i] = i; d_sq[i] = 0.f; }
    if (tid < Bg) d_gcount[tid] = d_gstart[tid+1] - d_gstart[tid];
}

// ---------------- transpose + fused squared norms ----------------
__global__ void k_transpose(int layer){
    const float* h = layer ? d_e : d_h;
    __shared__ float tile[32][33];
    int n0 = blockIdx.x*32, d0 = blockIdx.y*32;
    int tx = threadIdx.x, ty = threadIdx.y;       // (32,8)
    #pragma unroll
    for (int r = ty; r < 32; r += 8) tile[r][tx] = h[(n0+r)*Hd + d0 + tx];
    __syncthreads();
    #pragma unroll
    for (int r = ty; r < 32; r += 8) d_hT[(d0+r)*Nn + n0 + tx] = tile[tx][r];
    if (ty == 0){
        float ssum = 0.f;
        #pragma unroll 8
        for (int k = 0; k < 32; k++){ float v = tile[tx][k]; ssum = fmaf(v, v, ssum); }
        atomicAdd(&d_sq[n0+tx], ssum);
    }
}

// ---------------- kNN: 16 queries/block, scalar FMA distance, warp-per-query top-16 ----------------
extern __shared__ float knn_smem[];
__global__ void __launch_bounds__(512) k_knn(int layer){
    const float* h = layer ? d_e : d_h;
    float* dbuf = knn_smem;                 // [16][DPAD]
    float* hq   = knn_smem + 16*DPAD;       // [64][16]
    __shared__ int   qidx[16];
    __shared__ float sqq[16];
    __shared__ int   sh_g, sh_qs0;

    int tid = threadIdx.x;
    if (tid == 0){
        int bt = blockIdx.x, acc = 0, gg = -1, qq0 = 0;
        for (int g2 = 0; g2 < Bg; g2++){
            int cg = d_gcount[g2]; if (cg > DPAD) cg = DPAD;
            int tiles = (cg + 15) >> 4;
            if (bt < acc + tiles){ gg = g2; qq0 = (bt - acc)*16; break; }
            acc += tiles;
        }
        sh_g = gg; sh_qs0 = qq0;
    }
    __syncthreads();
    if (sh_g < 0) return;
    int g = sh_g, qs0 = sh_qs0;
    int p0  = d_gstart[g];
    int cnt = d_gcount[g]; if (cnt > DPAD) cnt = DPAD;
    int nq  = cnt - qs0; if (nq > 16) nq = 16;

    if (tid < 256){
        int q = tid >> 4, d4 = (tid & 15) << 2;
        int qq = (q < nq) ? q : (nq - 1);
        int qi = d_glist[p0 + qs0 + qq];
        float4 v = *(const float4*)&h[qi*Hd + d4];
        hq[(d4+0)*16+q] = v.x; hq[(d4+1)*16+q] = v.y;
        hq[(d4+2)*16+q] = v.z; hq[(d4+3)*16+q] = v.w;
        if (d4 == 0){ qidx[q] = qi; sqq[q] = d_sq[qi]; }
    }
    __syncthreads();

    for (int c0 = 0; c0 < cnt; c0 += 1024){
        int ca = c0 + tid, cb = ca + 512;
        int ja = (ca < cnt) ? d_glist[p0+ca] : d_glist[p0];
        int jb = (cb < cnt) ? d_glist[p0+cb] : d_glist[p0];
        float acc0[16], acc1[16];
        #pragma unroll
        for (int q = 0; q < 16; q++){ acc0[q] = 0.f; acc1[q] = 0.f; }
        const float* pa = d_hT + ja;
        const float* pb = d_hT + jb;
        const float4* hr = (const float4*)hq;
        #pragma unroll 2
        for (int d = 0; d < Hd; d++){
            float va = *pa; pa += Nn;
            float vb = *pb; pb += Nn;
            float4 q0 = hr[0], q1 = hr[1], q2 = hr[2], q3 = hr[3];
            hr += 4;
            KNN_FMA16(acc0, va, q0, q1, q2, q3)
            KNN_FMA16(acc1, vb, q0, q1, q2, q3)
        }
        if (ca < cnt){
            float sqa = d_sq[ja];
            #pragma unroll
            for (int q = 0; q < 16; q++) dbuf[q*DPAD+ca] = sqq[q] + sqa - 2.f*acc0[q];
        }
        if (cb < cnt){
            float sqb = d_sq[jb];
            #pragma unroll
            for (int q = 0; q < 16; q++) dbuf[q*DPAD+cb] = sqq[q] + sqb - 2.f*acc1[q];
        }
    }
    __syncthreads();

    int warp = tid >> 5, lane = tid & 31;
    if (warp < nq){
        float* row = &dbuf[warp*DPAD];
        int qi = qidx[warp];
        for (int r = 0; r < Kn; r++){
            float bd = INFINITY; int bp = 0x7fffffff;
            for (int c = lane; c < cnt; c += 32){
                float dd = row[c];
                if (dd < bd){ bd = dd; bp = c; }
            }
            #pragma unroll
            for (int off = 16; off > 0; off >>= 1){
                float od = __shfl_down_sync(0xffffffffu, bd, off);
                int   op = __shfl_down_sync(0xffffffffu, bp, off);
                if (od < bd || (od == bd && op < bp)){ bd = od; bp = op; }
            }
            int win = __shfl_sync(0xffffffffu, bp, 0);
            if (lane == 0) d_idx[qi*Kn + r] = d_glist[p0 + win];
            row[win] = INFINITY;
            __syncwarp();
        }
    }
}

// ---------------- edgeconv stage 1: scalar, 4 nodes per weight read ----------------
#define UVN 16
__global__ void __launch_bounds__(128) k_uv(int layer, const float* __restrict__ l0w,
                     const float* __restrict__ l0b,
                     const float* __restrict__ g0, const float* __restrict__ b0){
    const int t = threadIdx.x;
    const int* valid = layer ? d_validB : d_validA;
    const float* h   = layer ? d_e      : d_h;
    __shared__ float Wsh[H2*129];
    __shared__ float hsh[4][Hd];
    for (int p = t; p < H2*H2; p += H2){
        int o = p >> 7, c = p & 127;
        Wsh[o*129 + c] = __ldg(&l0w[p]);
    }
    float s  = __ldg(&g0[t]) / sqrtf(1.0f + BN_EPS);
    float bb = __ldg(&l0b[t])*s + __ldg(&b0[t]);
    __syncthreads();

    int base = blockIdx.x * UVN;
    for (int r4 = 0; r4 < UVN; r4 += 4){
        #pragma unroll
        for (int p = t; p < 4*Hd; p += 128){
            int n = p >> 6, c = p & 63;
            int i = base + r4 + n;
            hsh[n][c] = valid[i] ? h[i*Hd+c] : 0.f;
        }
        __syncthreads();
        const float* wr = &Wsh[t*129];
        float su0=0,su1=0,su2=0,su3=0, sv0=0,sv1=0,sv2=0,sv3=0;
        #pragma unroll 4
        for (int c = 0; c < Hd; c++){
            float a  = wr[c];
            float bw = wr[Hd+c];
            float amb = a - bw;
            float h0 = hsh[0][c], h1 = hsh[1][c], h2 = hsh[2][c], h3 = hsh[3][c];
            su0 = fmaf(h0, amb, su0); sv0 = fmaf(h0, bw, sv0);
            su1 = fmaf(h1, amb, su1); sv1 = fmaf(h1, bw, sv1);
            su2 = fmaf(h2, amb, su2); sv2 = fmaf(h2, bw, sv2);
            su3 = fmaf(h3, amb, su3); sv3 = fmaf(h3, bw, sv3);
        }
        int i0 = base + r4;
        if (valid[i0  ]){ d_u[(i0  )*H2+t] = su0*s + bb; d_v[(i0  )*H2+t] = sv0*s; }
        if (valid[i0+1]){ d_u[(i0+1)*H2+t] = su1*s + bb; d_v[(i0+1)*H2+t] = sv1*s; }
        if (valid[i0+2]){ d_u[(i0+2)*H2+t] = su2*s + bb; d_v[(i0+2)*H2+t] = sv2*s; }
        if (valid[i0+3]){ d_u[(i0+3)*H2+t] = su3*s + bb; d_v[(i0+3)*H2+t] = sv3*s; }
        __syncthreads();
    }
}

// ---------------- edgeconv stage 2: f32x2 mainloop (broadcast LDS => FMA-issue-bound) ----------------
#define EN 16
__global__ void __launch_bounds__(256) k_edge(int layer, const float* __restrict__ l1w,
                       const float* __restrict__ l1b,
                       const float* __restrict__ g1, const float* __restrict__ b1){
    const int tid = threadIdx.x;
    const int grp = tid >> 6, t = tid & 63, lane = tid & 31;
    const int* valid = layer ? d_validB : d_validA;
    float*     out   = layer ? d_h      : d_e;

    __shared__ float W1t[H2*65];
    __shared__ __align__(16) float rsh[4][H2*16];

    for (int p = tid; p < Hd*H2; p += 256){
        int o = p >> 7, r = p & 127;
        W1t[r*65+o] = __ldg(&l1w[p]);
    }
    float s  = __ldg(&g1[t]) / sqrtf(1.0f + BN_EPS);
    float bb = __ldg(&l1b[t])*s + __ldg(&b1[t]);
    __syncthreads();

    int base = blockIdx.x * EN;
    for (int round = 0; round < 4; round++){
        int i = base + round*4 + grp;
        if (!valid[i]) continue;

        float u0 = d_u[i*H2+t], u1 = d_u[i*H2+64+t];
        int myj = (lane < Kn) ? d_idx[i*Kn+lane] : 0;
        float r0[16], r1[16];
        #pragma unroll
        for (int e = 0; e < 16; e++){
            int j = __shfl_sync(0xffffffffu, myj, e);
            r0[e] = fmaxf(u0 + __ldg(&d_v[j*H2+t]),    0.f);
            r1[e] = fmaxf(u1 + __ldg(&d_v[j*H2+64+t]), 0.f);
        }
        float* R = rsh[grp];
        #pragma unroll
        for (int q = 0; q < 4; q++){
            *(float4*)&R[t*16+q*4]      = make_float4(r0[q*4],r0[q*4+1],r0[q*4+2],r0[q*4+3]);
            *(float4*)&R[(t+64)*16+q*4] = make_float4(r1[q*4],r1[q*4+1],r1[q*4+2],r1[q*4+3]);
        }
        asm volatile("bar.sync %0, 64;" :: "r"(grp+1) : "memory");

        unsigned long long acc2[8];
        #pragma unroll
        for (int q = 0; q < 8; q++) acc2[q] = 0ULL;
        const ulonglong2* Rr = (const ulonglong2*)R;
        #pragma unroll 2
        for (int r = 0; r < H2; r++){
            ulonglong2 pA = Rr[0], pB = Rr[1], pC = Rr[2], pD = Rr[3];
            Rr += 4;
            float w = W1t[r*65+t];
            unsigned long long w2; PACKF2(w2, w);
            FMA2(acc2[0], pA.x, w2); FMA2(acc2[1], pA.y, w2);
            FMA2(acc2[2], pB.x, w2); FMA2(acc2[3], pB.y, w2);
            FMA2(acc2[4], pC.x, w2); FMA2(acc2[5], pC.y, w2);
            FMA2(acc2[6], pD.x, w2); FMA2(acc2[7], pD.y, w2);
        }
        float o = 0.f;
        #pragma unroll
        for (int q = 0; q < 8; q++){
            unsigned int lo, hi; UNPACKF2(lo, hi, acc2[q]);
            o += fmaxf(__uint_as_float(lo)*s + bb, 0.f);
            o += fmaxf(__uint_as_float(hi)*s + bb, 0.f);
        }
        out[i*Hd+t] = o;
        asm volatile("bar.sync %0, 64;" :: "r"(grp+1) : "memory");
    }
}

// ---------------- cluster pool: mutual max-distance matching ----------------
__global__ void k_partner(int layer){
    const float* h     = layer ? d_h : d_e;
    const int*   valid = layer ? d_validB : d_validA;
    int lane = threadIdx.x & 31, wid = threadIdx.x >> 5;
    int i = blockIdx.x*4 + wid;
    if (!valid[i]){ if (lane == 0) d_partner[i] = i; return; }

    int n = lane & 15, hf = lane >> 4;
    int j = d_idx[i*Kn+n];
    const float4* pj = (const float4*)&h[j*Hd + hf*32];
    const float4* pi = (const float4*)&h[i*Hd + hf*32];
    float ssum = 0.f;
    #pragma unroll
    for (int q = 0; q < 8; q++){
        float4 a = __ldg(&pj[q]);
        float4 b = pi[q];
        float dx = a.x-b.x, dy = a.y-b.y, dz = a.z-b.z, dw = a.w-b.w;
        ssum += dx*dx + dy*dy + dz*dz + dw*dw;
    }
    ssum += __shfl_xor_sync(0xffffffffu, ssum, 16);
    float w = (j == i) ? -INFINITY : sqrtf(ssum + 1e-12f);
    int bk = n;
    #pragma unroll
    for (int off = 8; off > 0; off >>= 1){
        float ow = __shfl_down_sync(0xffffffffu, w,  off);
        int   ok = __shfl_down_sync(0xffffffffu, bk, off);
        int   oj = __shfl_down_sync(0xffffffffu, j,  off);
        if (ow > w || (ow == w && ok < bk)){ w = ow; bk = ok; j = oj; }
    }
    if (lane == 0) d_partner[i] = valid[j] ? j : i;
}

// ---------------- pool (parallel; also zeroes d_sq for next layer) ----------------
__global__ void k_pool(int layer){
    int tid = blockIdx.x*256 + threadIdx.x;
    int i = tid >> 6, t = tid & 63;
    float* h   = layer ? d_h : d_e;
    const int* vin  = layer ? d_validB : d_validA;
    int*       vout = layer ? d_validA : d_validB;
    if (t == 0) d_sq[i] = 0.f;
    if (!vin[i]){ if (t == 0) vout[i] = 0; return; }
    int p = d_partner[i];
    int keep = 1;
    if (p != i && d_partner[p] == i){
        if (p < i) keep = 0;
        else h[i*Hd+t] = fmaxf(h[i*Hd+t], h[p*Hd+t]);
    }
    if (t == 0) vout[i] = keep;
}

// ---------------- order-preserving compaction ----------------
__global__ void k_compact(){
    int g = blockIdx.x, t = threadIdx.x;
    int lane = t & 31, warp = t >> 5;
    int s = d_gstart[g], e2 = d_gstart[g+1];
    __shared__ int wsum[8], woff[8], base;
    if (t == 0) base = 0;
    __syncthreads();
    for (int st = s; st < e2; st += 256){
        int node = st + t;
        int f = (node < e2) ? d_validB[node] : 0;
        unsigned m = __ballot_sync(0xffffffffu, f);
        int wpre = __popc(m & ((1u << lane) - 1u));
        if (lane == 0) wsum[warp] = __popc(m);
        __syncthreads();
        if (t == 0){
            int r = base;
            for (int w2 = 0; w2 < 8; w2++){ woff[w2] = r; r += wsum[w2]; }
            base = r;
        }
        __syncthreads();
        if (f) d_glist[s + woff[warp] + wpre] = node;
        __syncthreads();
    }
    if (t == 0) d_gcount[g] = base;
}

// ---------------- global max-pool ----------------
__global__ void k_globalpool(){
    int b = blockIdx.x, t = threadIdx.x;
    int c = t & 63, rg = t >> 6;
    int s = d_gstart[b], e2 = d_gstart[b+1];
    float m = -1e30f;
    for (int i = s + rg; i < e2; i += 8)
        if (d_validA[i]) m = fmaxf(m, d_h[i*Hd+c]);
    __shared__ float red[512];
    red[t] = m; __syncthreads();
    if (t < 256) red[t] = fmaxf(red[t], red[t+256]);
    __syncthreads();
    if (t < 128) red[t] = fmaxf(red[t], red[t+128]);
    __syncthreads();
    if (t < 64) d_g[b*Hd + c] = fmaxf(red[t], red[t+64]);
}

// ---------------- output MLP ----------------
__global__ void k_mlp(const float* __restrict__ o0w, const float* __restrict__ o0b,
                      const float* __restrict__ o1w, const float* __restrict__ o1b,
                      const float* __restrict__ o2w, const float* __restrict__ o2b,
                      float* __restrict__ out){
    int t = threadIdx.x;
    int b = t >> 6, c = t & 63;
    __shared__ float g1s[Bg*Hd], g2s[Bg*Hd];
    float acc = __ldg(&o0b[c]);
    for (int d = 0; d < Hd; d++) acc += d_g[b*Hd+d] * __ldg(&o0w[c*Hd+d]);
    g1s[t] = fmaxf(acc, 0.f);
    __syncthreads();
    acc = __ldg(&o1b[c]);
    for (int d = 0; d < Hd; d++) acc += g1s[b*Hd+d] * __ldg(&o1w[c*Hd+d]);
    g2s[t] = fmaxf(acc, 0.f);
    __syncthreads();
    if (t < Bg){
        float a = __ldg(&o2b[0]);
        for (int d = 0; d < Hd; d++) a += g2s[t*Hd+d] * __ldg(&o2w[d]);
        out[t] = a;
    }
}

// ---------------- launch ----------------
extern "C" void kernel_launch(void* const* d_in, const int* in_sizes, int n_in,
                              void* d_out, int out_size){
    const float* x     = (const float*)d_in[0];
    const int*   batch = (const int*)  d_in[1];
    const float* dn    = (const float*)d_in[2];
    const float* inw   = (const float*)d_in[3];
    const float* inb   = (const float*)d_in[4];
    const float* A[2][8];
    for (int l = 0; l < 2; l++)
        for (int q = 0; q < 8; q++)
            A[l][q] = (const float*)d_in[5 + l*8 + q];
    const float* o0w = (const float*)d_in[21];
    const float* o0b = (const float*)d_in[22];
    const float* o1w = (const float*)d_in[23];
    const float* o1b = (const float*)d_in[24];
    const float* o2w = (const float*)d_in[25];
    const float* o2b = (const float*)d_in[26];
    float* out = (float*)d_out;

    const int knn_smem_bytes = (16*DPAD + Hd*16) * (int)sizeof(float);
    cudaFuncSetAttribute(k_knn, cudaFuncAttributeMaxDynamicSharedMemorySize, knn_smem_bytes);

    // launch order matters: ncu captures launch index 3 -> k_knn layer 0
    k_bounds<<<1, 32>>>(batch);                 // 0
    k_input<<<Nn/4, 256>>>(x, dn, inw, inb);    // 1 (init fused)

    dim3 tgrid(Nn/32, Hd/32), tthr(32, 8);
    for (int l = 0; l < 2; l++){
        k_transpose<<<tgrid, tthr>>>(l);        // 2 (sq fused)
        k_knn<<<MAXT, 512, knn_smem_bytes>>>(l);// 3 <- profiled
        k_uv<<<(Nn + UVN - 1)/UVN, H2>>>(l, A[l][0], A[l][1], A[l][2], A[l][3]);
        k_edge<<<(Nn + EN - 1)/EN, 256>>>(l, A[l][4], A[l][5], A[l][6], A[l][7]);
        k_partner<<<Nn/4, 128>>>(l);
        k_pool<<<Nn/4, 256>>>(l);
        if (l == 0) k_compact<<<Bg, 256>>>();
    }

    k_globalpool<<<Bg, 512>>>();
    k_mlp<<<1, Bg*Hd>>>(o0w, o0b, o1w, o1b, o2w, o2b, out);
}

// round 13
// speedup vs baseline: 1.1516x; 1.0641x over previous
#include <cuda_runtime.h>
#include <math.h>

#define Nn 16384
#define Bg 16
#define Hd 64
#define H2 128
#define Kn 16
#define DPAD 1280
#define MAXT 1600
#define NSLOT 40            // DPAD/32
#define BN_EPS 1e-5f

// packed f32x2 helpers (bit-exact pairs of IEEE fp32 FMAs)
#define FMA2(acc, a, b) asm("fma.rn.f32x2 %0, %1, %2, %0;" : "+l"(acc) : "l"(a), "l"(b))
#define PACKF2(dst, x)  asm("mov.b64 %0, {%1, %1};" : "=l"(dst) : "r"(__float_as_uint(x)))
#define UNPACKF2(lo, hi, src) asm("mov.b64 {%0, %1}, %2;" : "=r"(lo), "=r"(hi) : "l"(src))

// ---------------- scratch ----------------
__device__ float d_h[Nn*Hd];
__device__ float d_e[Nn*Hd];
__device__ float d_hT[Hd*Nn];
__device__ float d_u[Nn*H2];
__device__ float d_v[Nn*H2];
__device__ float d_sq[Nn];
__device__ float d_g[Bg*Hd];
__device__ float d_dist[Nn*DPAD];   // per-query-slot distance rows
__device__ int   d_idx[Nn*Kn];
__device__ int   d_partner[Nn];
__device__ int   d_validA[Nn];
__device__ int   d_validB[Nn];
__device__ int   d_gstart[Bg+1];
__device__ int   d_glist[Nn];
__device__ int   d_gcount[Bg];

// ---------------- graph bounds ----------------
__global__ void k_bounds(const int* __restrict__ batch){
    int b = threadIdx.x;
    if (b > Bg) return;
    if (b == Bg){ d_gstart[Bg] = Nn; return; }
    int lo = 0, hi = Nn;
    while (lo < hi){ int mid = (lo + hi) >> 1; if (batch[mid] < b) lo = mid + 1; else hi = mid; }
    d_gstart[b] = lo;
}

// ---------------- input net + init (fused) ----------------
__global__ void k_input(const float* __restrict__ x, const float* __restrict__ dn,
                        const float* __restrict__ w, const float* __restrict__ b){
    int tid = blockIdx.x*256 + threadIdx.x;
    int i = tid >> 6, c = tid & 63;
    float acc = __ldg(&b[c]);
    #pragma unroll
    for (int d = 0; d < 4; d++) acc += x[i*4+d] * __ldg(&dn[d]) * __ldg(&w[c*4+d]);
    d_h[i*Hd+c] = fmaxf(acc, 0.f);
    if (c == 0){ d_validA[i] = 1; d_glist[i] = i; d_sq[i] = 0.f; }
    if (tid < Bg) d_gcount[tid] = d_gstart[tid+1] - d_gstart[tid];
}

// ---------------- transpose + fused squared norms ----------------
__global__ void k_transpose(int layer){
    const float* h = layer ? d_e : d_h;
    __shared__ float tile[32][33];
    int n0 = blockIdx.x*32, d0 = blockIdx.y*32;
    int tx = threadIdx.x, ty = threadIdx.y;       // (32,8)
    #pragma unroll
    for (int r = ty; r < 32; r += 8) tile[r][tx] = h[(n0+r)*Hd + d0 + tx];
    __syncthreads();
    #pragma unroll
    for (int r = ty; r < 32; r += 8) d_hT[(d0+r)*Nn + n0 + tx] = tile[tx][r];
    if (ty == 0){
        float ssum = 0.f;
        #pragma unroll 8
        for (int k = 0; k < 32; k++){ float v = tile[tx][k]; ssum = fmaf(v, v, ssum); }
        atomicAdd(&d_sq[n0+tx], ssum);
    }
}

// ---------------- kNN distances: 16 queries/block, 256 threads, f32x2 ----------------
__global__ void __launch_bounds__(256) k_dist(int layer){
    const float* h = layer ? d_e : d_h;
    __shared__ __align__(16) float hq[Hd*16];     // [d][16]
    __shared__ int   qidx0;                        // first query slot
    __shared__ float sqq[16];
    __shared__ int   sh_g, sh_qs0;

    int tid = threadIdx.x;
    if (tid == 0){
        int bt = blockIdx.x, acc = 0, gg = -1, qq0 = 0;
        for (int g2 = 0; g2 < Bg; g2++){
            int cg = d_gcount[g2]; if (cg > DPAD) cg = DPAD;
            int tiles = (cg + 15) >> 4;
            if (bt < acc + tiles){ gg = g2; qq0 = (bt - acc)*16; break; }
            acc += tiles;
        }
        sh_g = gg; sh_qs0 = qq0;
    }
    __syncthreads();
    if (sh_g < 0) return;
    int g = sh_g, qs0 = sh_qs0;
    int p0  = d_gstart[g];
    int cnt = d_gcount[g]; if (cnt > DPAD) cnt = DPAD;
    int nq  = cnt - qs0; if (nq > 16) nq = 16;

    {   // stage query features [d][16] (padded queries duplicate last -> benign same-value races)
        int q = tid >> 4, d4 = (tid & 15) << 2;
        int qq = (q < nq) ? q : (nq - 1);
        int qi = d_glist[p0 + qs0 + qq];
        float4 v = *(const float4*)&h[qi*Hd + d4];
        hq[(d4+0)*16+q] = v.x; hq[(d4+1)*16+q] = v.y;
        hq[(d4+2)*16+q] = v.z; hq[(d4+3)*16+q] = v.w;
        if (d4 == 0) sqq[q] = d_sq[qi];
        if (tid == 0) qidx0 = p0 + qs0;
    }
    __syncthreads();
    int s0 = qidx0;

    for (int c0 = 0; c0 < cnt; c0 += 256){
        int ca = c0 + tid;
        int ja = (ca < cnt) ? d_glist[p0+ca] : d_glist[p0];
        unsigned long long acc2[8];
        #pragma unroll
        for (int q = 0; q < 8; q++) acc2[q] = 0ULL;
        const float* pa = d_hT + ja;
        const ulonglong2* hr = (const ulonglong2*)hq;
        #pragma unroll 4
        for (int d = 0; d < Hd; d++){
            float va = *pa; pa += Nn;
            unsigned long long va2; PACKF2(va2, va);
            ulonglong2 qA = hr[0], qB = hr[1], qC = hr[2], qD = hr[3];
            hr += 4;
            FMA2(acc2[0], qA.x, va2); FMA2(acc2[1], qA.y, va2);
            FMA2(acc2[2], qB.x, va2); FMA2(acc2[3], qB.y, va2);
            FMA2(acc2[4], qC.x, va2); FMA2(acc2[5], qC.y, va2);
            FMA2(acc2[6], qD.x, va2); FMA2(acc2[7], qD.y, va2);
        }
        if (ca < cnt){
            float sqa = d_sq[ja];
            #pragma unroll
            for (int q = 0; q < 8; q++){
                unsigned int lo, hi; UNPACKF2(lo, hi, acc2[q]);
                int qa = 2*q, qb = 2*q+1;
                if (qa < nq) d_dist[(s0+qa)*DPAD + ca] = sqq[qa] + sqa - 2.f*__uint_as_float(lo);
                if (qb < nq) d_dist[(s0+qb)*DPAD + ca] = sqq[qb] + sqa - 2.f*__uint_as_float(hi);
            }
        }
    }
}

// ---------------- kNN selection: warp per query slot, register-cached top-16 ----------------
__global__ void __launch_bounds__(256) k_sel(int layer){
    int warp = threadIdx.x >> 5, lane = threadIdx.x & 31;
    int s = blockIdx.x*8 + warp;                  // query slot

    // locate graph of slot s (uniform within warp)
    int g = 0;
    #pragma unroll
    for (int gg = 1; gg < Bg; gg++) if (d_gstart[gg] <= s) g = gg;
    int p0  = d_gstart[g];
    int cnt = d_gcount[g]; if (cnt > DPAD) cnt = DPAD;
    if (s >= p0 + cnt) return;                    // dead slot

    int qi = d_glist[s];
    const float* row = d_dist + (long)s*DPAD;

    // register cache: lane owns candidates c = lane + 32k
    float v[NSLOT];
    #pragma unroll
    for (int k = 0; k < NSLOT; k++){
        int c = lane + 32*k;
        v[k] = (c < cnt) ? row[c] : INFINITY;
    }

    for (int r = 0; r < Kn; r++){
        float bd = INFINITY; int bc = 0x7fffffff;
        #pragma unroll
        for (int k = 0; k < NSLOT; k++){
            if (v[k] < bd){ bd = v[k]; bc = lane + 32*k; }   // ascending k => smallest c in lane
        }
        #pragma unroll
        for (int off = 16; off > 0; off >>= 1){
            float od = __shfl_down_sync(0xffffffffu, bd, off);
            int   oc = __shfl_down_sync(0xffffffffu, bc, off);
            if (od < bd || (od == bd && oc < bc)){ bd = od; bc = oc; }
        }
        int win = __shfl_sync(0xffffffffu, bc, 0);
        if (lane == 0) d_idx[qi*Kn + r] = d_glist[p0 + win];
        if (lane == (win & 31)){
            int ks = win >> 5;
            #pragma unroll
            for (int k = 0; k < NSLOT; k++) if (k == ks) v[k] = INFINITY;
        }
    }
}

// ---------------- edgeconv stage 1: scalar, 4 nodes per weight read ----------------
#define UVN 16
__global__ void __launch_bounds__(128) k_uv(int layer, const float* __restrict__ l0w,
                     const float* __restrict__ l0b,
                     const float* __restrict__ g0, const float* __restrict__ b0){
    const int t = threadIdx.x;
    const int* valid = layer ? d_validB : d_validA;
    const float* h   = layer ? d_e      : d_h;
    __shared__ float Wsh[H2*129];
    __shared__ float hsh[4][Hd];
    for (int p = t; p < H2*H2; p += H2){
        int o = p >> 7, c = p & 127;
        Wsh[o*129 + c] = __ldg(&l0w[p]);
    }
    float s  = __ldg(&g0[t]) / sqrtf(1.0f + BN_EPS);
    float bb = __ldg(&l0b[t])*s + __ldg(&b0[t]);
    __syncthreads();

    int base = blockIdx.x * UVN;
    for (int r4 = 0; r4 < UVN; r4 += 4){
        #pragma unroll
        for (int p = t; p < 4*Hd; p += 128){
            int n = p >> 6, c = p & 63;
            int i = base + r4 + n;
            hsh[n][c] = valid[i] ? h[i*Hd+c] : 0.f;
        }
        __syncthreads();
        const float* wr = &Wsh[t*129];
        float su0=0,su1=0,su2=0,su3=0, sv0=0,sv1=0,sv2=0,sv3=0;
        #pragma unroll 4
        for (int c = 0; c < Hd; c++){
            float a  = wr[c];
            float bw = wr[Hd+c];
            float amb = a - bw;
            float h0 = hsh[0][c], h1 = hsh[1][c], h2 = hsh[2][c], h3 = hsh[3][c];
            su0 = fmaf(h0, amb, su0); sv0 = fmaf(h0, bw, sv0);
            su1 = fmaf(h1, amb, su1); sv1 = fmaf(h1, bw, sv1);
            su2 = fmaf(h2, amb, su2); sv2 = fmaf(h2, bw, sv2);
            su3 = fmaf(h3, amb, su3); sv3 = fmaf(h3, bw, sv3);
        }
        int i0 = base + r4;
        if (valid[i0  ]){ d_u[(i0  )*H2+t] = su0*s + bb; d_v[(i0  )*H2+t] = sv0*s; }
        if (valid[i0+1]){ d_u[(i0+1)*H2+t] = su1*s + bb; d_v[(i0+1)*H2+t] = sv1*s; }
        if (valid[i0+2]){ d_u[(i0+2)*H2+t] = su2*s + bb; d_v[(i0+2)*H2+t] = sv2*s; }
        if (valid[i0+3]){ d_u[(i0+3)*H2+t] = su3*s + bb; d_v[(i0+3)*H2+t] = sv3*s; }
        __syncthreads();
    }
}

// ---------------- edgeconv stage 2: f32x2 mainloop ----------------
#define EN 16
__global__ void __launch_bounds__(256) k_edge(int layer, const float* __restrict__ l1w,
                       const float* __restrict__ l1b,
                       const float* __restrict__ g1, const float* __restrict__ b1){
    const int tid = threadIdx.x;
    const int grp = tid >> 6, t = tid & 63, lane = tid & 31;
    const int* valid = layer ? d_validB : d_validA;
    float*     out   = layer ? d_h      : d_e;

    __shared__ float W1t[H2*65];
    __shared__ __align__(16) float rsh[4][H2*16];

    for (int p = tid; p < Hd*H2; p += 256){
        int o = p >> 7, r = p & 127;
        W1t[r*65+o] = __ldg(&l1w[p]);
    }
    float s  = __ldg(&g1[t]) / sqrtf(1.0f + BN_EPS);
    float bb = __ldg(&l1b[t])*s + __ldg(&b1[t]);
    __syncthreads();

    int base = blockIdx.x * EN;
    for (int round = 0; round < 4; round++){
        int i = base + round*4 + grp;
        if (!valid[i]) continue;

        float u0 = d_u[i*H2+t], u1 = d_u[i*H2+64+t];
        int myj = (lane < Kn) ? d_idx[i*Kn+lane] : 0;
        float r0[16], r1[16];
        #pragma unroll
        for (int e = 0; e < 16; e++){
            int j = __shfl_sync(0xffffffffu, myj, e);
            r0[e] = fmaxf(u0 + __ldg(&d_v[j*H2+t]),    0.f);
            r1[e] = fmaxf(u1 + __ldg(&d_v[j*H2+64+t]), 0.f);
        }
        float* R = rsh[grp];
        #pragma unroll
        for (int q = 0; q < 4; q++){
            *(float4*)&R[t*16+q*4]      = make_float4(r0[q*4],r0[q*4+1],r0[q*4+2],r0[q*4+3]);
            *(float4*)&R[(t+64)*16+q*4] = make_float4(r1[q*4],r1[q*4+1],r1[q*4+2],r1[q*4+3]);
        }
        asm volatile("bar.sync %0, 64;" :: "r"(grp+1) : "memory");

        unsigned long long acc2[8];
        #pragma unroll
        for (int q = 0; q < 8; q++) acc2[q] = 0ULL;
        const ulonglong2* Rr = (const ulonglong2*)R;
        #pragma unroll 2
        for (int r = 0; r < H2; r++){
            ulonglong2 pA = Rr[0], pB = Rr[1], pC = Rr[2], pD = Rr[3];
            Rr += 4;
            float w = W1t[r*65+t];
            unsigned long long w2; PACKF2(w2, w);
            FMA2(acc2[0], pA.x, w2); FMA2(acc2[1], pA.y, w2);
            FMA2(acc2[2], pB.x, w2); FMA2(acc2[3], pB.y, w2);
            FMA2(acc2[4], pC.x, w2); FMA2(acc2[5], pC.y, w2);
            FMA2(acc2[6], pD.x, w2); FMA2(acc2[7], pD.y, w2);
        }
        float o = 0.f;
        #pragma unroll
        for (int q = 0; q < 8; q++){
            unsigned int lo, hi; UNPACKF2(lo, hi, acc2[q]);
            o += fmaxf(__uint_as_float(lo)*s + bb, 0.f);
            o += fmaxf(__uint_as_float(hi)*s + bb, 0.f);
        }
        out[i*Hd+t] = o;
        asm volatile("bar.sync %0, 64;" :: "r"(grp+1) : "memory");
    }
}

// ---------------- cluster pool: mutual max-distance matching ----------------
__global__ void k_partner(int layer){
    const float* h     = layer ? d_h : d_e;
    const int*   valid = layer ? d_validB : d_validA;
    int lane = threadIdx.x & 31, wid = threadIdx.x >> 5;
    int i = blockIdx.x*4 + wid;
    if (!valid[i]){ if (lane == 0) d_partner[i] = i; return; }

    int n = lane & 15, hf = lane >> 4;
    int j = d_idx[i*Kn+n];
    const float4* pj = (const float4*)&h[j*Hd + hf*32];
    const float4* pi = (const float4*)&h[i*Hd + hf*32];
    float ssum = 0.f;
    #pragma unroll
    for (int q = 0; q < 8; q++){
        float4 a = __ldg(&pj[q]);
        float4 b = pi[q];
        float dx = a.x-b.x, dy = a.y-b.y, dz = a.z-b.z, dw = a.w-b.w;
        ssum += dx*dx + dy*dy + dz*dz + dw*dw;
    }
    ssum += __shfl_xor_sync(0xffffffffu, ssum, 16);
    float w = (j == i) ? -INFINITY : sqrtf(ssum + 1e-12f);
    int bk = n;
    #pragma unroll
    for (int off = 8; off > 0; off >>= 1){
        float ow = __shfl_down_sync(0xffffffffu, w,  off);
        int   ok = __shfl_down_sync(0xffffffffu, bk, off);
        int   oj = __shfl_down_sync(0xffffffffu, j,  off);
        if (ow > w || (ow == w && ok < bk)){ w = ow; bk = ok; j = oj; }
    }
    if (lane == 0) d_partner[i] = valid[j] ? j : i;
}

// ---------------- pool (parallel; also zeroes d_sq for next layer) ----------------
__global__ void k_pool(int layer){
    int tid = blockIdx.x*256 + threadIdx.x;
    int i = tid >> 6, t = tid & 63;
    float* h   = layer ? d_h : d_e;
    const int* vin  = layer ? d_validB : d_validA;
    int*       vout = layer ? d_validA : d_validB;
    if (t == 0) d_sq[i] = 0.f;
    if (!vin[i]){ if (t == 0) vout[i] = 0; return; }
    int p = d_partner[i];
    int keep = 1;
    if (p != i && d_partner[p] == i){
        if (p < i) keep = 0;
        else h[i*Hd+t] = fmaxf(h[i*Hd+t], h[p*Hd+t]);
    }
    if (t == 0) vout[i] = keep;
}

// ---------------- order-preserving compaction ----------------
__global__ void k_compact(){
    int g = blockIdx.x, t = threadIdx.x;
    int lane = t & 31, warp = t >> 5;
    int s = d_gstart[g], e2 = d_gstart[g+1];
    __shared__ int wsum[8], woff[8], base;
    if (t == 0) base = 0;
    __syncthreads();
    for (int st = s; st < e2; st += 256){
        int node = st + t;
        int f = (node < e2) ? d_validB[node] : 0;
        unsigned m = __ballot_sync(0xffffffffu, f);
        int wpre = __popc(m & ((1u << lane) - 1u));
        if (lane == 0) wsum[warp] = __popc(m);
        __syncthreads();
        if (t == 0){
            int r = base;
            for (int w2 = 0; w2 < 8; w2++){ woff[w2] = r; r += wsum[w2]; }
            base = r;
        }
        __syncthreads();
        if (f) d_glist[s + woff[warp] + wpre] = node;
        __syncthreads();
    }
    if (t == 0) d_gcount[g] = base;
}

// ---------------- global max-pool ----------------
__global__ void k_globalpool(){
    int b = blockIdx.x, t = threadIdx.x;
    int c = t & 63, rg = t >> 6;
    int s = d_gstart[b], e2 = d_gstart[b+1];
    float m = -1e30f;
    for (int i = s + rg; i < e2; i += 8)
        if (d_validA[i]) m = fmaxf(m, d_h[i*Hd+c]);
    __shared__ float red[512];
    red[t] = m; __syncthreads();
    if (t < 256) red[t] = fmaxf(red[t], red[t+256]);
    __syncthreads();
    if (t < 128) red[t] = fmaxf(red[t], red[t+128]);
    __syncthreads();
    if (t < 64) d_g[b*Hd + c] = fmaxf(red[t], red[t+64]);
}

// ---------------- output MLP ----------------
__global__ void k_mlp(const float* __restrict__ o0w, const float* __restrict__ o0b,
                      const float* __restrict__ o1w, const float* __restrict__ o1b,
                      const float* __restrict__ o2w, const float* __restrict__ o2b,
                      float* __restrict__ out){
    int t = threadIdx.x;
    int b = t >> 6, c = t & 63;
    __shared__ float g1s[Bg*Hd], g2s[Bg*Hd];
    float acc = __ldg(&o0b[c]);
    for (int d = 0; d < Hd; d++) acc += d_g[b*Hd+d] * __ldg(&o0w[c*Hd+d]);
    g1s[t] = fmaxf(acc, 0.f);
    __syncthreads();
    acc = __ldg(&o1b[c]);
    for (int d = 0; d < Hd; d++) acc += g1s[b*Hd+d] * __ldg(&o1w[c*Hd+d]);
    g2s[t] = fmaxf(acc, 0.f);
    __syncthreads();
    if (t < Bg){
        float a = __ldg(&o2b[0]);
        for (int d = 0; d < Hd; d++) a += g2s[t*Hd+d] * __ldg(&o2w[d]);
        out[t] = a;
    }
}

// ---------------- launch ----------------
extern "C" void kernel_launch(void* const* d_in, const int* in_sizes, int n_in,
                              void* d_out, int out_size){
    const float* x     = (const float*)d_in[0];
    const int*   batch = (const int*)  d_in[1];
    const float* dn    = (const float*)d_in[2];
    const float* inw   = (const float*)d_in[3];
    const float* inb   = (const float*)d_in[4];
    const float* A[2][8];
    for (int l = 0; l < 2; l++)
        for (int q = 0; q < 8; q++)
            A[l][q] = (const float*)d_in[5 + l*8 + q];
    const float* o0w = (const float*)d_in[21];
    const float* o0b = (const float*)d_in[22];
    const float* o1w = (const float*)d_in[23];
    const float* o1b = (const float*)d_in[24];
    const float* o2w = (const float*)d_in[25];
    const float* o2b = (const float*)d_in[26];
    float* out = (float*)d_out;

    k_bounds<<<1, 32>>>(batch);                 // 0
    k_input<<<Nn/4, 256>>>(x, dn, inw, inb);    // 1

    dim3 tgrid(Nn/32, Hd/32), tthr(32, 8);
    for (int l = 0; l < 2; l++){
        k_transpose<<<tgrid, tthr>>>(l);        // 2
        k_dist<<<MAXT, 256>>>(l);               // 3 <- profiled slot
        k_sel<<<Nn/8, 256>>>(l);
        k_uv<<<(Nn + UVN - 1)/UVN, H2>>>(l, A[l][0], A[l][1], A[l][2], A[l][3]);
        k_edge<<<(Nn + EN - 1)/EN, 256>>>(l, A[l][4], A[l][5], A[l][6], A[l][7]);
        k_partner<<<Nn/4, 128>>>(l);
        k_pool<<<Nn/4, 256>>>(l);
        if (l == 0) k_compact<<<Bg, 256>>>();
    }

    k_globalpool<<<Bg, 512>>>();
    k_mlp<<<1, Bg*Hd>>>(o0w, o0b, o1w, o1b, o2w, o2b, out);
}